// round 4
// baseline (speedup 1.0000x reference)
#include <cuda_runtime.h>
#include <math.h>
#include <math_constants.h>

// Problem constants
#define NB 2
#define NS 2048
#define ND 2048
#define NH 16
#define DH 128
#define NM 4096   // NB*NS

// log2(10000)/64
#define L2_10K_OVER_64 0.2076205059304602f
// 1/sqrt(128)
#define QSCALE 0.08838834764831845f

// Scratch: sanctioned __device__ globals (no runtime allocation).
__device__ float g_q [NB*NH*NS*DH];
__device__ float g_k [NB*NH*NS*DH];
__device__ float g_v [NB*NH*NS*DH];
__device__ float g_ao[NB*NS*ND];

// ---------------------------------------------------------------------------
// SGEMM: C(4096x2048) = A(4096x2048) @ B(2048x2048), 128x128x16 tiles,
// 256 threads, 8x8 microtile per thread.
// MODE 0: Q proj  -> rope + 1/sqrt(HD) scale, (B,H,S,HD) layout
// MODE 1: K proj  -> rope,                    (B,H,S,HD) layout
// MODE 2: V proj  -> plain,                   (B,H,S,HD) layout
// MODE 3: plain row-major store (output projection)
// ---------------------------------------------------------------------------
template<int MODE>
__global__ void __launch_bounds__(256) gemm_kernel(const float* __restrict__ A,
                                                   const float* __restrict__ B,
                                                   float* __restrict__ C) {
    __shared__ float As[16][132];   // A tile transposed: As[k][m]
    __shared__ float Bs[16][136];   // B tile: Bs[k][n]

    const int tid  = threadIdx.x;
    const int tr   = tid >> 4;      // 0..15 (row group)
    const int tc   = tid & 15;      // 0..15 (col group)
    const int row0 = blockIdx.y * 128;
    const int col0 = blockIdx.x * 128;

    const float* Ab = A + (size_t)row0 * ND;
    const float* Bb = B + col0;

    float acc[8][8];
#pragma unroll
    for (int i = 0; i < 8; ++i)
#pragma unroll
        for (int j = 0; j < 8; ++j) acc[i][j] = 0.f;

    for (int k0 = 0; k0 < ND; k0 += 16) {
        // Load A tile 128x16 (transposed into smem)
#pragma unroll
        for (int it = 0; it < 2; ++it) {
            int idx = tid + it * 256;          // 0..511
            int r   = idx >> 2;                // 0..127
            int c   = (idx & 3) << 2;          // 0,4,8,12
            float4 v = *(const float4*)(Ab + (size_t)r * ND + k0 + c);
            As[c + 0][r] = v.x;
            As[c + 1][r] = v.y;
            As[c + 2][r] = v.z;
            As[c + 3][r] = v.w;
        }
        // Load B tile 16x128
#pragma unroll
        for (int it = 0; it < 2; ++it) {
            int idx = tid + it * 256;
            int kk  = idx >> 5;                // 0..15
            int c   = (idx & 31) << 2;         // 0..124
            *(float4*)&Bs[kk][c] = *(const float4*)(Bb + (size_t)(k0 + kk) * ND + c);
        }
        __syncthreads();

#pragma unroll
        for (int kk = 0; kk < 16; ++kk) {
            float a[8], b[8];
            *(float4*)(a)     = *(const float4*)&As[kk][tr * 8];
            *(float4*)(a + 4) = *(const float4*)&As[kk][tr * 8 + 4];
            *(float4*)(b)     = *(const float4*)&Bs[kk][tc * 8];
            *(float4*)(b + 4) = *(const float4*)&Bs[kk][tc * 8 + 4];
#pragma unroll
            for (int i = 0; i < 8; ++i)
#pragma unroll
                for (int j = 0; j < 8; ++j)
                    acc[i][j] = fmaf(a[i], b[j], acc[i][j]);
        }
        __syncthreads();
    }

    if (MODE == 3) {
#pragma unroll
        for (int i = 0; i < 8; ++i) {
            float* dst = C + (size_t)(row0 + tr * 8 + i) * ND + col0 + tc * 8;
            *(float4*)(dst)     = *(float4*)&acc[i][0];
            *(float4*)(dst + 4) = *(float4*)&acc[i][4];
        }
    } else {
        const int e0    = col0 + tc * 8;     // global output column base
        const int h     = e0 >> 7;           // head (constant per thread)
        const int dbase = e0 & 127;          // head-dim base (even)

        float invf[8];
        if (MODE != 2) {
#pragma unroll
            for (int j = 0; j < 8; ++j) {
                int dm = (dbase + j) & 63;
                invf[j] = exp2f(-(float)dm * L2_10K_OVER_64);
            }
        }

#pragma unroll
        for (int i = 0; i < 8; ++i) {
            int m  = row0 + tr * 8 + i;      // global row = b*S + s
            int bb = m >> 11;
            int ss = m & 2047;
            float* dst = C + (((size_t)(bb * NH + h) * NS + ss) << 7) + dbase;
            if (MODE == 2) {
                *(float4*)(dst)     = *(float4*)&acc[i][0];
                *(float4*)(dst + 4) = *(float4*)&acc[i][4];
            } else {
                float pos = (float)ss;
#pragma unroll
                for (int j = 0; j < 8; j += 2) {
                    float s0, c0, s1, c1;
                    sincosf(pos * invf[j],     &s0, &c0);
                    sincosf(pos * invf[j + 1], &s1, &c1);
                    float v0 = acc[i][j], v1 = acc[i][j + 1];
                    // out_even = x_e*cos(a_e) - x_o*sin(a_e)
                    // out_odd  = x_o*cos(a_o) + x_e*sin(a_o)
                    float o0 = v0 * c0 - v1 * s0;
                    float o1 = v1 * c1 + v0 * s1;
                    if (MODE == 0) { o0 *= QSCALE; o1 *= QSCALE; }
                    dst[j]     = o0;
                    dst[j + 1] = o1;
                }
            }
        }
    }
}

// ---------------------------------------------------------------------------
// Flash attention: 64x64 tiles, online softmax, fp32.
// grid = (S/64, H, B), 256 threads (16x16), thread owns 4 score rows x 4 cols
// and 4 O rows x 8 O cols. Q pre-scaled by 1/sqrt(HD), Q/K pre-roped.
// Output layout (B,S,H,HD) so the final GEMM reads it row-major (4096x2048).
// ---------------------------------------------------------------------------
__global__ void __launch_bounds__(256) flash_kernel(const float* __restrict__ Q,
                                                    const float* __restrict__ K,
                                                    const float* __restrict__ V,
                                                    float* __restrict__ O) {
    extern __shared__ float sm[];
    float* Qst = sm;                   // [128][65] transposed Q tile
    float* Kst = Qst + 128 * 65;       // [128][65] transposed K tile
    float* Vsm = Kst + 128 * 65;       // [64][136] row-major V tile
    float* Ps  = Vsm + 64 * 136;       // [64][65]  probability tile

    const int tid = threadIdx.x;
    const int ty  = tid >> 4;          // 0..15
    const int tx  = tid & 15;          // 0..15
    const int q0  = blockIdx.x * 64;
    const int h   = blockIdx.y;
    const int b   = blockIdx.z;

    const size_t headoff = (size_t)(b * NH + h) * NS * DH;
    const float* Qb = Q + headoff + (size_t)q0 * DH;

    // Load Q tile (transposed, odd pitch -> conflict-free scalar stores)
    for (int idx = tid; idx < 64 * 128; idx += 256) {
        int d = idx & 127, r = idx >> 7;
        Qst[d * 65 + r] = Qb[r * DH + d];
    }

    float o[4][8];
    float mrow[4], lrow[4];
#pragma unroll
    for (int i = 0; i < 4; ++i) {
        mrow[i] = -CUDART_INF_F;
        lrow[i] = 0.f;
#pragma unroll
        for (int j = 0; j < 8; ++j) o[i][j] = 0.f;
    }

    for (int n0 = 0; n0 <= q0; n0 += 64) {
        const float* Kb = K + headoff + (size_t)n0 * DH;
        const float* Vb = V + headoff + (size_t)n0 * DH;
        for (int idx = tid; idx < 64 * 128; idx += 256) {
            int d = idx & 127, r = idx >> 7;
            Kst[d * 65 + r] = Kb[r * DH + d];
        }
        for (int idx = tid; idx < 64 * 32; idx += 256) {
            int r = idx >> 5, c = (idx & 31) << 2;
            *(float4*)&Vsm[r * 136 + c] = *(const float4*)(Vb + r * DH + c);
        }
        __syncthreads();

        // S = Q K^T (Q already scaled)
        float sacc[4][4];
#pragma unroll
        for (int i = 0; i < 4; ++i)
#pragma unroll
            for (int j = 0; j < 4; ++j) sacc[i][j] = 0.f;

#pragma unroll 4
        for (int k = 0; k < 128; ++k) {
            float a[4], bf[4];
#pragma unroll
            for (int i = 0; i < 4; ++i) a[i] = Qst[k * 65 + 4 * ty + i];
#pragma unroll
            for (int j = 0; j < 4; ++j) bf[j] = Kst[k * 65 + 4 * tx + j];
#pragma unroll
            for (int i = 0; i < 4; ++i)
#pragma unroll
                for (int j = 0; j < 4; ++j)
                    sacc[i][j] = fmaf(a[i], bf[j], sacc[i][j]);
        }

        // Causal mask: only the diagonal tile needs it
        if (n0 == q0) {
#pragma unroll
            for (int i = 0; i < 4; ++i)
#pragma unroll
                for (int j = 0; j < 4; ++j)
                    if (4 * tx + j > 4 * ty + i) sacc[i][j] = -CUDART_INF_F;
        }

        // Online softmax per row (16 lanes per row group; xor-shuffles <16
        // stay inside the group)
#pragma unroll
        for (int i = 0; i < 4; ++i) {
            float mt = fmaxf(fmaxf(sacc[i][0], sacc[i][1]),
                             fmaxf(sacc[i][2], sacc[i][3]));
#pragma unroll
            for (int off = 8; off; off >>= 1)
                mt = fmaxf(mt, __shfl_xor_sync(0xffffffffu, mt, off));
            float mn    = fmaxf(mrow[i], mt);
            float alpha = expf(mrow[i] - mn);   // first tile: exp(-inf)=0
            float rs = 0.f;
#pragma unroll
            for (int j = 0; j < 4; ++j) {
                float p = expf(sacc[i][j] - mn);
                Ps[(4 * ty + i) * 65 + 4 * tx + j] = p;
                rs += p;
            }
#pragma unroll
            for (int off = 8; off; off >>= 1)
                rs += __shfl_xor_sync(0xffffffffu, rs, off);
            lrow[i] = lrow[i] * alpha + rs;
            mrow[i] = mn;
#pragma unroll
            for (int j = 0; j < 8; ++j) o[i][j] *= alpha;
        }
        __syncthreads();

        // O += P V
#pragma unroll 2
        for (int k = 0; k < 64; ++k) {
            float vv[8];
            *(float4*)(vv)     = *(float4*)&Vsm[k * 136 + 8 * tx];
            *(float4*)(vv + 4) = *(float4*)&Vsm[k * 136 + 8 * tx + 4];
#pragma unroll
            for (int i = 0; i < 4; ++i) {
                float p = Ps[(4 * ty + i) * 65 + k];
#pragma unroll
                for (int j = 0; j < 8; ++j)
                    o[i][j] = fmaf(p, vv[j], o[i][j]);
            }
        }
        __syncthreads();
    }

    // Normalize and store as (B,S,H,HD)
#pragma unroll
    for (int i = 0; i < 4; ++i) {
        float il = 1.f / lrow[i];
        int s = q0 + 4 * ty + i;
        float* dst = O + ((size_t)(b * NS + s) * NH + h) * DH + 8 * tx;
#pragma unroll
        for (int j = 0; j < 8; ++j) dst[j] = o[i][j] * il;
    }
}

// ---------------------------------------------------------------------------
extern "C" void kernel_launch(void* const* d_in, const int* in_sizes, int n_in,
                              void* d_out, int out_size) {
    const float* x  = (const float*)d_in[0];
    const float* Wq = (const float*)d_in[1];
    const float* Wk = (const float*)d_in[2];
    const float* Wv = (const float*)d_in[3];
    const float* Wo = (const float*)d_in[4];

    float *qp, *kp, *vp, *aop;
    cudaGetSymbolAddress((void**)&qp,  g_q);
    cudaGetSymbolAddress((void**)&kp,  g_k);
    cudaGetSymbolAddress((void**)&vp,  g_v);
    cudaGetSymbolAddress((void**)&aop, g_ao);

    dim3 gg(ND / 128, NM / 128);

    gemm_kernel<0><<<gg, 256>>>(x, Wq, qp);
    gemm_kernel<1><<<gg, 256>>>(x, Wk, kp);
    gemm_kernel<2><<<gg, 256>>>(x, Wv, vp);

    const int smem = (2 * 128 * 65 + 64 * 136 + 64 * 65) * (int)sizeof(float); // 118016 B
    cudaFuncSetAttribute(flash_kernel,
                         cudaFuncAttributeMaxDynamicSharedMemorySize, smem);
    flash_kernel<<<dim3(NS / 64, NH, NB), 256, smem>>>(qp, kp, vp, aop);

    gemm_kernel<3><<<gg, 256>>>(aop, Wo, (float*)d_out);
}